// round 10
// baseline (speedup 1.0000x reference)
#include <cuda_runtime.h>
#include <cuda_bf16.h>
#include <stdint.h>

#define NNODES 100000
#define H1DIM 128
#define H2DIM 64
#define BN_EPS 1e-5f
#define PAD 136
#define EMAX (1 << 20)
#define TILE 64
#define NTILES ((NNODES + TILE - 1) / TILE)   // 1563
#define NPERS 148

// ---------------- scratch ----------------
__device__ int   g_degi[NNODES];
__device__ float g_dinv[NNODES];
__device__ int   g_rowptr[NNODES + 2];
__device__ int   g_cursor[NNODES];
__device__ int   g_blksum[512];
__device__ int   g_blkoff[512];
__device__ int   g_esrc[EMAX];
__device__ float g_enorm[EMAX];
__device__ float g_h2[(size_t)NNODES * H2DIM];
__device__ float g_bns[H1DIM];
__device__ float g_bnt[H1DIM];
__device__ __align__(16) __nv_bfloat16 g_w1h[128 * 128];  // W1^T hi [n][k]
__device__ __align__(16) __nv_bfloat16 g_w1l[128 * 128];
__device__ __align__(16) __nv_bfloat16 g_w2h[64 * 128];
__device__ __align__(16) __nv_bfloat16 g_w2l[64 * 128];
__device__ int   g_is64;

// ---------------- helpers ----------------
__device__ __forceinline__ void mma_bf16(float* c, const uint32_t* a, uint32_t b0, uint32_t b1) {
    asm volatile("mma.sync.aligned.m16n8k16.row.col.f32.bf16.bf16.f32 "
                 "{%0,%1,%2,%3}, {%4,%5,%6,%7}, {%8,%9}, {%0,%1,%2,%3};"
                 : "+f"(c[0]), "+f"(c[1]), "+f"(c[2]), "+f"(c[3])
                 : "r"(a[0]), "r"(a[1]), "r"(a[2]), "r"(a[3]), "r"(b0), "r"(b1));
}
__device__ __forceinline__ void ldsm_x4(uint32_t& r0, uint32_t& r1, uint32_t& r2, uint32_t& r3,
                                        uint32_t addr) {
    asm volatile("ldmatrix.sync.aligned.m8n8.x4.shared.b16 {%0,%1,%2,%3}, [%4];"
                 : "=r"(r0), "=r"(r1), "=r"(r2), "=r"(r3) : "r"(addr));
}
#define BAR_SYNC(id, n)   asm volatile("bar.sync %0, %1;" :: "r"(id), "r"(n) : "memory")
#define BAR_ARRIVE(id, n) asm volatile("bar.arrive %0, %1;" :: "r"(id), "r"(n) : "memory")

__device__ __forceinline__ void split1(float v, __nv_bfloat16& hi, __nv_bfloat16& lo) {
    hi = __float2bfloat16_rn(v);
    lo = __float2bfloat16_rn(v - __bfloat162float(hi));
}
__device__ __forceinline__ void split2_packed(float a, float b, uint32_t& hi, uint32_t& lo) {
    __nv_bfloat16 ha, la, hb, lb;
    split1(a, ha, la);
    split1(b, hb, lb);
    hi = (uint32_t)__bfloat16_as_ushort(ha) | ((uint32_t)__bfloat16_as_ushort(hb) << 16);
    lo = (uint32_t)__bfloat16_as_ushort(la) | ((uint32_t)__bfloat16_as_ushort(lb) << 16);
}
__device__ __forceinline__ int ld_idx(const void* p, long long i) {
    if (g_is64) return (int)((const long long*)p)[i];
    return ((const int*)p)[i];
}

// ---------------- detect dtype + W split (degi self-resets in dinv_scan1) ----------------
__global__ void detectw_kernel(const void* ei, const float* __restrict__ W1,
                               const float* __restrict__ W2) {
    int i = blockIdx.x * blockDim.x + threadIdx.x;
    if (i == 0) {
        const long long* p = (const long long*)ei;
        int is64 = 1;
        for (int j = 0; j < 64; j++) {
            long long v = p[j];
            if (v < 0 || v >= (long long)NNODES) { is64 = 0; break; }
        }
        g_is64 = is64;
    }
    if (i < 128 * 128) {
        int k = i >> 7, n = i & 127;
        __nv_bfloat16 hb, lb;
        split1(W1[k * 128 + n], hb, lb);
        g_w1h[n * 128 + k] = hb;
        g_w1l[n * 128 + k] = lb;
    }
    if (i < 128 * 64) {
        int k = i >> 6, n = i & 63;
        __nv_bfloat16 hb, lb;
        split1(W2[k * 64 + n], hb, lb);
        g_w2h[n * 128 + k] = hb;
        g_w2l[n * 128 + k] = lb;
    }
}

__global__ void deg_count_kernel(const void* ei, int E) {
    int e = blockIdx.x * blockDim.x + threadIdx.x;
    if (e < E) atomicAdd(&g_degi[ld_idx(ei, (long long)E + e)], 1);
}

// ---------------- dinv + BN + scan phase 1 (and reset degi for next replay) ----------------
__global__ void dinv_scan1_kernel(const float* __restrict__ b1,
                                  const float* __restrict__ gamma,
                                  const float* __restrict__ beta,
                                  const float* __restrict__ rmean,
                                  const float* __restrict__ rvar) {
    __shared__ int sm[256];
    int i = blockIdx.x * 256 + threadIdx.x;
    int v = 0;
    if (i < NNODES) {
        v = g_degi[i];
        g_degi[i] = 0;                       // self-reset for next launch
        g_dinv[i] = rsqrtf((float)v + 1.0f);
    }
    if (i < H1DIM) {
        float s = gamma[i] * rsqrtf(rvar[i] + BN_EPS);
        g_bns[i] = s;
        g_bnt[i] = (b1[i] - rmean[i]) * s + beta[i];
    }
    sm[threadIdx.x] = v;
    __syncthreads();
    for (int off = 1; off < 256; off <<= 1) {
        int t = (threadIdx.x >= off) ? sm[threadIdx.x - off] : 0;
        __syncthreads();
        sm[threadIdx.x] += t;
        __syncthreads();
    }
    if (i < NNODES) g_rowptr[i] = sm[threadIdx.x] - v;
    if (threadIdx.x == 255) g_blksum[blockIdx.x] = sm[255];
}
__global__ void scan2_kernel(int nb) {
    __shared__ int sm[512];
    int v = (threadIdx.x < nb) ? g_blksum[threadIdx.x] : 0;
    sm[threadIdx.x] = v;
    __syncthreads();
    for (int off = 1; off < 512; off <<= 1) {
        int t = (threadIdx.x >= off) ? sm[threadIdx.x - off] : 0;
        __syncthreads();
        sm[threadIdx.x] += t;
        __syncthreads();
    }
    if (threadIdx.x < nb) g_blkoff[threadIdx.x] = sm[threadIdx.x] - v;
}
__global__ void scan3_kernel(int E) {
    int i = blockIdx.x * blockDim.x + threadIdx.x;
    if (i < NNODES) {
        int r = g_rowptr[i] + g_blkoff[i >> 8];
        g_rowptr[i] = r;
        g_cursor[i] = r;
    }
    if (i == 0) { g_rowptr[NNODES] = E; g_rowptr[NNODES + 1] = E; }
}
__global__ void permute_kernel(const void* __restrict__ ei, int E) {
    int e = blockIdx.x * blockDim.x + threadIdx.x;
    if (e >= E) return;
    int s = ld_idx(ei, e);
    int d = ld_idx(ei, (long long)E + e);
    float nm = g_dinv[s] * g_dinv[d];
    int pos = atomicAdd(&g_cursor[d], 1);
    g_esrc[pos] = s;
    g_enorm[pos] = nm;
}

// ---------------- persistent warp-specialized fused kernel ----------------
// smem (bf16 elems): [buf0_hi][buf0_lo][buf1_hi][buf1_lo] each 64*PAD, then W1 hi/lo 128*PAD, W2 hi/lo 64*PAD
#define SMF_W1H (4 * 64 * PAD)
#define SMF_W1L (SMF_W1H + 128 * PAD)
#define SMF_W2H (SMF_W1L + 128 * PAD)
#define SMF_W2L (SMF_W2H + 64 * PAD)
#define SMF_TOTAL ((SMF_W2L + 64 * PAD) * 2)

__global__ void __launch_bounds__(512) fused_kernel(const float* __restrict__ x) {
    extern __shared__ __nv_bfloat16 sm[];
    const uint32_t sbase = (uint32_t)__cvta_generic_to_shared(sm);
    const int tid = threadIdx.x, wid = tid >> 5, lid = tid & 31;

    // W copies (all threads)
    for (int i = tid; i < 128 * 16; i += 512) {
        int r = i >> 4, c = i & 15;
        *(uint4*)&sm[SMF_W1H + r * PAD + c * 8] = ((const uint4*)g_w1h)[r * 16 + c];
        *(uint4*)&sm[SMF_W1L + r * PAD + c * 8] = ((const uint4*)g_w1l)[r * 16 + c];
    }
    for (int i = tid; i < 64 * 16; i += 512) {
        int r = i >> 4, c = i & 15;
        *(uint4*)&sm[SMF_W2H + r * PAD + c * 8] = ((const uint4*)g_w2h)[r * 16 + c];
        *(uint4*)&sm[SMF_W2L + r * PAD + c * 8] = ((const uint4*)g_w2l)[r * 16 + c];
    }
    __syncthreads();

    const float4* xr = (const float4*)x;
    const bool producer = (wid < 8);

    if (producer) {
        int it = 0;
        for (int tile = blockIdx.x; tile < NTILES; tile += NPERS, it++) {
            int b = it & 1;
            if (it >= 2) BAR_SYNC(3 + b, 512);
            const int bufh = b * 2 * 64 * PAD;
            const int bufl = bufh + 64 * PAD;
            // warp handles rows [wid*8, wid*8+8) as 4 node pairs
#pragma unroll 1
            for (int pair = 0; pair < 4; pair++) {
                int rl0 = wid * 8 + pair * 2;
                int n0 = tile * TILE + rl0, n1 = n0 + 1;
                float4 acc0 = make_float4(0.f, 0.f, 0.f, 0.f);
                float4 acc1 = make_float4(0.f, 0.f, 0.f, 0.f);
                int beg0 = 0, end0 = 0, end1 = 0;
                if (n0 < NNODES) {
                    beg0 = g_rowptr[n0];
                    end0 = g_rowptr[n0 + 1];
                    end1 = g_rowptr[n0 + 2];
                    float di0 = g_dinv[n0];
                    acc0 = xr[(size_t)n0 * 32 + lid];
                    acc0.x *= di0 * di0; acc0.y *= di0 * di0;
                    acc0.z *= di0 * di0; acc0.w *= di0 * di0;
                    if (n1 < NNODES) {
                        float di1 = g_dinv[n1];
                        acc1 = xr[(size_t)n1 * 32 + lid];
                        acc1.x *= di1 * di1; acc1.y *= di1 * di1;
                        acc1.z *= di1 * di1; acc1.w *= di1 * di1;
                    } else {
                        end1 = end0;
                    }
                }
                int j = beg0;
                for (; j + 4 <= end1; j += 4) {
                    int s0 = g_esrc[j], s1 = g_esrc[j + 1], s2 = g_esrc[j + 2], s3 = g_esrc[j + 3];
                    float m0 = g_enorm[j], m1 = g_enorm[j + 1], m2 = g_enorm[j + 2], m3 = g_enorm[j + 3];
                    float4 v0 = xr[(size_t)s0 * 32 + lid];
                    float4 v1 = xr[(size_t)s1 * 32 + lid];
                    float4 v2 = xr[(size_t)s2 * 32 + lid];
                    float4 v3 = xr[(size_t)s3 * 32 + lid];
                    float4* a0 = (j + 0 < end0) ? &acc0 : &acc1;
                    float4* a1 = (j + 1 < end0) ? &acc0 : &acc1;
                    float4* a2 = (j + 2 < end0) ? &acc0 : &acc1;
                    float4* a3 = (j + 3 < end0) ? &acc0 : &acc1;
                    a0->x += v0.x * m0; a0->y += v0.y * m0; a0->z += v0.z * m0; a0->w += v0.w * m0;
                    a1->x += v1.x * m1; a1->y += v1.y * m1; a1->z += v1.z * m1; a1->w += v1.w * m1;
                    a2->x += v2.x * m2; a2->y += v2.y * m2; a2->z += v2.z * m2; a2->w += v2.w * m2;
                    a3->x += v3.x * m3; a3->y += v3.y * m3; a3->z += v3.z * m3; a3->w += v3.w * m3;
                }
                for (; j < end1; j++) {
                    int s0 = g_esrc[j];
                    float m0 = g_enorm[j];
                    float4 v0 = xr[(size_t)s0 * 32 + lid];
                    float4* a = (j < end0) ? &acc0 : &acc1;
                    a->x += v0.x * m0; a->y += v0.y * m0; a->z += v0.z * m0; a->w += v0.w * m0;
                }
                uint32_t h0a, l0a, h0b, l0b;
                split2_packed(acc0.x, acc0.y, h0a, l0a);
                split2_packed(acc0.z, acc0.w, h0b, l0b);
                *(uint2*)&sm[bufh + rl0 * PAD + lid * 4] = make_uint2(h0a, h0b);
                *(uint2*)&sm[bufl + rl0 * PAD + lid * 4] = make_uint2(l0a, l0b);
                uint32_t h1a, l1a, h1b, l1b;
                split2_packed(acc1.x, acc1.y, h1a, l1a);
                split2_packed(acc1.z, acc1.w, h1b, l1b);
                *(uint2*)&sm[bufh + (rl0 + 1) * PAD + lid * 4] = make_uint2(h1a, h1b);
                *(uint2*)&sm[bufl + (rl0 + 1) * PAD + lid * 4] = make_uint2(l1a, l1b);
            }
            BAR_ARRIVE(1 + b, 512);
        }
    } else {
        // consumers: warps 8..15, grid 2(row)x4(col)
        const int w8 = wid - 8;
        const int cw_r = w8 >> 2, cw_c = w8 & 3;
        const int g = lid >> 2, tg = lid & 3;
        const int ar0 = cw_r * 32;
        const int m4 = lid >> 3;
        const int arow = (m4 & 1) * 8 + (lid & 7);
        const int acol = (m4 >> 1) * 8;
        const uint32_t relA0 = (uint32_t)(((ar0 + arow) * PAD + acol) * 2);
        const uint32_t relA1 = (uint32_t)(((ar0 + 16 + arow) * PAD + acol) * 2);
        const int brow = (m4 >> 1) * 8 + (lid & 7);
        const int bcol = (m4 & 1) * 8;
        const int nc1 = cw_c * 32;
        uint32_t offB1[2];
#pragma unroll
        for (int bi = 0; bi < 2; bi++)
            offB1[bi] = sbase + 2 * (uint32_t)(SMF_W1H + (nc1 + bi * 16 + brow) * PAD + bcol);
        const uint32_t offB1L[2] = { offB1[0] + 2 * (uint32_t)(128 * PAD),
                                     offB1[1] + 2 * (uint32_t)(128 * PAD) };
        const int nc2 = cw_c * 16;
        const uint32_t offB2 = sbase + 2 * (uint32_t)(SMF_W2H + (nc2 + brow) * PAD + bcol);
        const uint32_t offB2L = offB2 + 2 * (uint32_t)(64 * PAD);

        int it = 0;
        for (int tile = blockIdx.x; tile < NTILES; tile += NPERS, it++) {
            int b = it & 1;
            BAR_SYNC(1 + b, 512);
            const uint32_t bufh = sbase + 2 * (uint32_t)(b * 2 * 64 * PAD);
            const uint32_t bufl = bufh + 2 * (uint32_t)(64 * PAD);

            // ---- MMA1: 64x128 ----
            float acc[2][4][4];
#pragma unroll
            for (int mi = 0; mi < 2; mi++)
#pragma unroll
                for (int ni = 0; ni < 4; ni++)
#pragma unroll
                    for (int q = 0; q < 4; q++) acc[mi][ni][q] = 0.f;

#pragma unroll 1
            for (int pass = 0; pass < 3; pass++) {
                uint32_t abase = (pass == 2) ? bufl : bufh;
                const uint32_t* bb = (pass == 1) ? offB1L : offB1;
#pragma unroll 1
                for (int ks = 0; ks < 8; ks++) {
                    uint32_t kb = (uint32_t)ks * 32;
                    uint32_t a0[4], a1[4];
                    ldsm_x4(a0[0], a0[1], a0[2], a0[3], abase + relA0 + kb);
                    ldsm_x4(a1[0], a1[1], a1[2], a1[3], abase + relA1 + kb);
#pragma unroll
                    for (int bi = 0; bi < 2; bi++) {
                        uint32_t b0, b1, b2, b3;
                        ldsm_x4(b0, b1, b2, b3, bb[bi] + kb);
                        mma_bf16(acc[0][2 * bi], a0, b0, b1);
                        mma_bf16(acc[0][2 * bi + 1], a0, b2, b3);
                        mma_bf16(acc[1][2 * bi], a1, b0, b1);
                        mma_bf16(acc[1][2 * bi + 1], a1, b2, b3);
                    }
                }
            }

            BAR_SYNC(5, 256);  // consumers done reading A
            // BN + ReLU + split -> overwrite A planes
            __nv_bfloat16* smh = (__nv_bfloat16*)sm + (size_t)(b * 2 * 64 * PAD);
            __nv_bfloat16* sml = smh + 64 * PAD;
#pragma unroll
            for (int mi = 0; mi < 2; mi++)
#pragma unroll
                for (int h = 0; h < 2; h++) {
                    int rl = ar0 + mi * 16 + h * 8 + g;
#pragma unroll
                    for (int ni = 0; ni < 4; ni++) {
                        int c = nc1 + ni * 8 + tg * 2;
                        float2 sc = *(const float2*)&g_bns[c];
                        float2 tc = *(const float2*)&g_bnt[c];
                        float v0 = fmaxf(acc[mi][ni][h * 2] * sc.x + tc.x, 0.f);
                        float v1 = fmaxf(acc[mi][ni][h * 2 + 1] * sc.y + tc.y, 0.f);
                        uint32_t hi, lo;
                        split2_packed(v0, v1, hi, lo);
                        *(uint32_t*)&smh[rl * PAD + c] = hi;
                        *(uint32_t*)&sml[rl * PAD + c] = lo;
                    }
                }
            BAR_SYNC(5, 256);  // H visible to all consumers

            // ---- MMA2: 64x64 ----
            float acc2[2][2][4];
#pragma unroll
            for (int mi = 0; mi < 2; mi++)
#pragma unroll
                for (int ni = 0; ni < 2; ni++)
#pragma unroll
                    for (int q = 0; q < 4; q++) acc2[mi][ni][q] = 0.f;

#pragma unroll 1
            for (int pass = 0; pass < 3; pass++) {
                uint32_t abase = (pass == 2) ? bufl : bufh;
                uint32_t bb = (pass == 1) ? offB2L : offB2;
#pragma unroll 1
                for (int ks = 0; ks < 8; ks++) {
                    uint32_t kb = (uint32_t)ks * 32;
                    uint32_t a0[4], a1[4];
                    ldsm_x4(a0[0], a0[1], a0[2], a0[3], abase + relA0 + kb);
                    ldsm_x4(a1[0], a1[1], a1[2], a1[3], abase + relA1 + kb);
                    uint32_t b0, b1, b2, b3;
                    ldsm_x4(b0, b1, b2, b3, bb + kb);
                    mma_bf16(acc2[0][0], a0, b0, b1);
                    mma_bf16(acc2[0][1], a0, b2, b3);
                    mma_bf16(acc2[1][0], a1, b0, b1);
                    mma_bf16(acc2[1][1], a1, b2, b3);
                }
            }
            BAR_ARRIVE(3 + b, 512);  // buffer free for producers

#pragma unroll
            for (int mi = 0; mi < 2; mi++)
#pragma unroll
                for (int h = 0; h < 2; h++) {
                    int r = tile * TILE + ar0 + mi * 16 + g + h * 8;
                    if (r < NNODES) {
#pragma unroll
                        for (int ni = 0; ni < 2; ni++) {
                            int c = nc2 + ni * 8 + tg * 2;
                            *(float2*)&g_h2[(size_t)r * 64 + c] =
                                make_float2(acc2[mi][ni][h * 2], acc2[mi][ni][h * 2 + 1]);
                        }
                    }
                }
        }
    }
}

// ---------------- agg2: half-warp per node ----------------
__global__ void __launch_bounds__(256) agg2_kernel(const float* __restrict__ b2,
                                                   float* __restrict__ out) {
    int t = blockIdx.x * blockDim.x + threadIdx.x;
    int hw = t >> 4;
    int sub = t & 15;
    if (hw >= NNODES) return;
    int beg = g_rowptr[hw], end = g_rowptr[hw + 1];
    float di = g_dinv[hw];
    float d2 = di * di;
    const float4* h2 = (const float4*)g_h2;
    float4 acc = h2[(size_t)hw * 16 + sub];
    acc.x *= d2; acc.y *= d2; acc.z *= d2; acc.w *= d2;
    int j = beg;
    for (; j + 4 <= end; j += 4) {
        int s0 = g_esrc[j], s1 = g_esrc[j + 1], s2 = g_esrc[j + 2], s3 = g_esrc[j + 3];
        float n0 = g_enorm[j], n1 = g_enorm[j + 1], n2 = g_enorm[j + 2], n3 = g_enorm[j + 3];
        float4 v0 = h2[(size_t)s0 * 16 + sub];
        float4 v1 = h2[(size_t)s1 * 16 + sub];
        float4 v2 = h2[(size_t)s2 * 16 + sub];
        float4 v3 = h2[(size_t)s3 * 16 + sub];
        acc.x += v0.x * n0 + v1.x * n1 + v2.x * n2 + v3.x * n3;
        acc.y += v0.y * n0 + v1.y * n1 + v2.y * n2 + v3.y * n3;
        acc.z += v0.z * n0 + v1.z * n1 + v2.z * n2 + v3.z * n3;
        acc.w += v0.w * n0 + v1.w * n1 + v2.w * n2 + v3.w * n3;
    }
    for (; j < end; j++) {
        int s0 = g_esrc[j];
        float n0 = g_enorm[j];
        float4 v0 = h2[(size_t)s0 * 16 + sub];
        acc.x += v0.x * n0; acc.y += v0.y * n0; acc.z += v0.z * n0; acc.w += v0.w * n0;
    }
    float4 bv = ((const float4*)b2)[sub];
    ((float4*)out)[(size_t)hw * 16 + sub] =
        make_float4(acc.x + bv.x, acc.y + bv.y, acc.z + bv.z, acc.w + bv.w);
}

// ---------------- launch ----------------
extern "C" void kernel_launch(void* const* d_in, const int* in_sizes, int n_in,
                              void* d_out, int out_size) {
    const float* x     = (const float*)d_in[0];
    const void*  ei    = d_in[1];
    const float* W1    = (const float*)d_in[2];
    const float* b1    = (const float*)d_in[3];
    const float* gamma = (const float*)d_in[4];
    const float* beta  = (const float*)d_in[5];
    const float* rmean = (const float*)d_in[6];
    const float* rvar  = (const float*)d_in[7];
    const float* W2    = (const float*)d_in[8];
    const float* b2    = (const float*)d_in[9];
    float* out = (float*)d_out;

    const int E = in_sizes[1] / 2;

    cudaFuncSetAttribute(fused_kernel, cudaFuncAttributeMaxDynamicSharedMemorySize, SMF_TOTAL);

    int nblk = (NNODES + 255) / 256;  // 391
    detectw_kernel<<<64, 256>>>(ei, W1, W2);
    deg_count_kernel<<<(E + 255) / 256, 256>>>(ei, E);
    dinv_scan1_kernel<<<nblk, 256>>>(b1, gamma, beta, rmean, rvar);
    scan2_kernel<<<1, 512>>>(nblk);
    scan3_kernel<<<nblk, 256>>>(E);
    permute_kernel<<<(E + 255) / 256, 256>>>(ei, E);

    fused_kernel<<<NPERS, 512, SMF_TOTAL>>>(x);

    {
        long long th = (long long)NNODES * 16;
        agg2_kernel<<<(int)((th + 255) / 256), 256>>>(b2, out);
    }
}

// round 11
// speedup vs baseline: 1.0337x; 1.0337x over previous
#include <cuda_runtime.h>
#include <cuda_bf16.h>
#include <stdint.h>

#define NNODES 100000
#define H1DIM 128
#define H2DIM 64
#define BN_EPS 1e-5f
#define PAD 136
#define EMAX (1 << 20)

// ---------------- scratch ----------------
__device__ int   g_degi[NNODES];
__device__ float g_dinv[NNODES];
__device__ int   g_rowptr[NNODES + 2];
__device__ int   g_cursor[NNODES];
__device__ int   g_blksum[512];
__device__ int   g_blkoff[512];
__device__ int   g_esrc[EMAX];
__device__ float g_enorm[EMAX];
__device__ float g_h2[(size_t)NNODES * H2DIM];
__device__ float g_bns[H1DIM];
__device__ float g_bnt[H1DIM];
__device__ __align__(16) __nv_bfloat16 g_w1h[128 * 128];  // W1^T hi [n][k]
__device__ __align__(16) __nv_bfloat16 g_w1l[128 * 128];
__device__ __align__(16) __nv_bfloat16 g_w2h[64 * 128];
__device__ __align__(16) __nv_bfloat16 g_w2l[64 * 128];
__device__ int   g_is64;

// ---------------- helpers ----------------
__device__ __forceinline__ void mma_bf16(float* c, const uint32_t* a, uint32_t b0, uint32_t b1) {
    asm volatile("mma.sync.aligned.m16n8k16.row.col.f32.bf16.bf16.f32 "
                 "{%0,%1,%2,%3}, {%4,%5,%6,%7}, {%8,%9}, {%0,%1,%2,%3};"
                 : "+f"(c[0]), "+f"(c[1]), "+f"(c[2]), "+f"(c[3])
                 : "r"(a[0]), "r"(a[1]), "r"(a[2]), "r"(a[3]), "r"(b0), "r"(b1));
}
__device__ __forceinline__ void ldsm_x4(uint32_t& r0, uint32_t& r1, uint32_t& r2, uint32_t& r3,
                                        uint32_t addr) {
    asm volatile("ldmatrix.sync.aligned.m8n8.x4.shared.b16 {%0,%1,%2,%3}, [%4];"
                 : "=r"(r0), "=r"(r1), "=r"(r2), "=r"(r3) : "r"(addr));
}
__device__ __forceinline__ void split1(float v, __nv_bfloat16& hi, __nv_bfloat16& lo) {
    hi = __float2bfloat16_rn(v);
    lo = __float2bfloat16_rn(v - __bfloat162float(hi));
}
__device__ __forceinline__ void split2_packed(float a, float b, uint32_t& hi, uint32_t& lo) {
    __nv_bfloat16 ha, la, hb, lb;
    split1(a, ha, la);
    split1(b, hb, lb);
    hi = (uint32_t)__bfloat16_as_ushort(ha) | ((uint32_t)__bfloat16_as_ushort(hb) << 16);
    lo = (uint32_t)__bfloat16_as_ushort(la) | ((uint32_t)__bfloat16_as_ushort(lb) << 16);
}
__device__ __forceinline__ int ld_idx(const void* p, long long i) {
    if (g_is64) return (int)((const long long*)p)[i];
    return ((const int*)p)[i];
}

// ---------------- detect dtype + W split ----------------
__global__ void detectw_kernel(const void* ei, const float* __restrict__ W1,
                               const float* __restrict__ W2) {
    int i = blockIdx.x * blockDim.x + threadIdx.x;
    if (i == 0) {
        const long long* p = (const long long*)ei;
        int is64 = 1;
        for (int j = 0; j < 64; j++) {
            long long v = p[j];
            if (v < 0 || v >= (long long)NNODES) { is64 = 0; break; }
        }
        g_is64 = is64;
    }
    if (i < 128 * 128) {
        int k = i >> 7, n = i & 127;
        __nv_bfloat16 hb, lb;
        split1(W1[k * 128 + n], hb, lb);
        g_w1h[n * 128 + k] = hb;
        g_w1l[n * 128 + k] = lb;
    }
    if (i < 128 * 64) {
        int k = i >> 6, n = i & 63;
        __nv_bfloat16 hb, lb;
        split1(W2[k * 64 + n], hb, lb);
        g_w2h[n * 128 + k] = hb;
        g_w2l[n * 128 + k] = lb;
    }
}

__global__ void deg_count_kernel(const void* ei, int E) {
    int e = blockIdx.x * blockDim.x + threadIdx.x;
    if (e < E) atomicAdd(&g_degi[ld_idx(ei, (long long)E + e)], 1);
}

// ---------------- dinv + BN + scan phase 1 (resets degi for next replay) ----------------
__global__ void dinv_scan1_kernel(const float* __restrict__ b1,
                                  const float* __restrict__ gamma,
                                  const float* __restrict__ beta,
                                  const float* __restrict__ rmean,
                                  const float* __restrict__ rvar) {
    __shared__ int sm[256];
    int i = blockIdx.x * 256 + threadIdx.x;
    int v = 0;
    if (i < NNODES) {
        v = g_degi[i];
        g_degi[i] = 0;
        g_dinv[i] = rsqrtf((float)v + 1.0f);
    }
    if (i < H1DIM) {
        float s = gamma[i] * rsqrtf(rvar[i] + BN_EPS);
        g_bns[i] = s;
        g_bnt[i] = (b1[i] - rmean[i]) * s + beta[i];
    }
    sm[threadIdx.x] = v;
    __syncthreads();
    for (int off = 1; off < 256; off <<= 1) {
        int t = (threadIdx.x >= off) ? sm[threadIdx.x - off] : 0;
        __syncthreads();
        sm[threadIdx.x] += t;
        __syncthreads();
    }
    if (i < NNODES) g_rowptr[i] = sm[threadIdx.x] - v;
    if (threadIdx.x == 255) g_blksum[blockIdx.x] = sm[255];
}
__global__ void scan2_kernel(int nb) {
    __shared__ int sm[512];
    int v = (threadIdx.x < nb) ? g_blksum[threadIdx.x] : 0;
    sm[threadIdx.x] = v;
    __syncthreads();
    for (int off = 1; off < 512; off <<= 1) {
        int t = (threadIdx.x >= off) ? sm[threadIdx.x - off] : 0;
        __syncthreads();
        sm[threadIdx.x] += t;
        __syncthreads();
    }
    if (threadIdx.x < nb) g_blkoff[threadIdx.x] = sm[threadIdx.x] - v;
}
__global__ void scan3_kernel(int E) {
    int i = blockIdx.x * blockDim.x + threadIdx.x;
    if (i < NNODES) {
        int r = g_rowptr[i] + g_blkoff[i >> 8];
        g_rowptr[i] = r;
        g_cursor[i] = r;
    }
    if (i == 0) { g_rowptr[NNODES] = E; g_rowptr[NNODES + 1] = E; }
}
__global__ void permute_kernel(const void* __restrict__ ei, int E) {
    int e = blockIdx.x * blockDim.x + threadIdx.x;
    if (e >= E) return;
    int s = ld_idx(ei, e);
    int d = ld_idx(ei, (long long)E + e);
    float nm = g_dinv[s] * g_dinv[d];
    int pos = atomicAdd(&g_cursor[d], 1);
    g_esrc[pos] = s;
    g_enorm[pos] = nm;
}

// ---------------- fused: gather(x) -> MMA1 -> BN/ReLU -> MMA2 -> h2 ----------------
// 512 threads = 16 warps, 128-row tiles.
#define SMF_AHI 0
#define SMF_ALO (128 * PAD)
#define SMF_W1H (2 * 128 * PAD)
#define SMF_W1L (3 * 128 * PAD)
#define SMF_W2H (4 * 128 * PAD)
#define SMF_W2L (4 * 128 * PAD + 64 * PAD)
#define SMF_TOTAL ((4 * 128 * PAD + 2 * 64 * PAD) * 2)

__global__ void __launch_bounds__(512) fused_kernel(const float* __restrict__ x) {
    extern __shared__ __nv_bfloat16 sm[];
    const uint32_t sbase = (uint32_t)__cvta_generic_to_shared(sm);
    const int tid = threadIdx.x, wid = tid >> 5, lid = tid & 31;
    const int row0 = blockIdx.x * 128;

    // W copies
    for (int i = tid; i < 128 * 16; i += 512) {
        int r = i >> 4, c = i & 15;
        *(uint4*)&sm[SMF_W1H + r * PAD + c * 8] = ((const uint4*)g_w1h)[r * 16 + c];
        *(uint4*)&sm[SMF_W1L + r * PAD + c * 8] = ((const uint4*)g_w1l)[r * 16 + c];
    }
    for (int i = tid; i < 64 * 16; i += 512) {
        int r = i >> 4, c = i & 15;
        *(uint4*)&sm[SMF_W2H + r * PAD + c * 8] = ((const uint4*)g_w2h)[r * 16 + c];
        *(uint4*)&sm[SMF_W2L + r * PAD + c * 8] = ((const uint4*)g_w2l)[r * 16 + c];
    }

    // ---- gather phase: warp handles 8 local rows as 4 node pairs, unroll-8 ----
    const float4* xr = (const float4*)x;
#pragma unroll 1
    for (int pair = 0; pair < 4; pair++) {
        int rl0 = wid * 8 + pair * 2;
        int n0 = row0 + rl0, n1 = n0 + 1;
        float4 acc0 = make_float4(0.f, 0.f, 0.f, 0.f);
        float4 acc1 = make_float4(0.f, 0.f, 0.f, 0.f);
        int beg0 = 0, end0 = 0, end1 = 0;
        if (n0 < NNODES) {
            beg0 = g_rowptr[n0];
            end0 = g_rowptr[n0 + 1];
            end1 = g_rowptr[n0 + 2];
            float di0 = g_dinv[n0];
            acc0 = xr[(size_t)n0 * 32 + lid];
            acc0.x *= di0 * di0; acc0.y *= di0 * di0;
            acc0.z *= di0 * di0; acc0.w *= di0 * di0;
            if (n1 < NNODES) {
                float di1 = g_dinv[n1];
                acc1 = xr[(size_t)n1 * 32 + lid];
                acc1.x *= di1 * di1; acc1.y *= di1 * di1;
                acc1.z *= di1 * di1; acc1.w *= di1 * di1;
            } else {
                end1 = end0;
            }
        }
        int j = beg0;
        for (; j + 8 <= end1; j += 8) {
            int   s[8];
            float m[8];
            float4 v[8];
#pragma unroll
            for (int q = 0; q < 8; q++) { s[q] = g_esrc[j + q]; m[q] = g_enorm[j + q]; }
#pragma unroll
            for (int q = 0; q < 8; q++) v[q] = xr[(size_t)s[q] * 32 + lid];
#pragma unroll
            for (int q = 0; q < 8; q++) {
                float4* a = (j + q < end0) ? &acc0 : &acc1;
                a->x += v[q].x * m[q]; a->y += v[q].y * m[q];
                a->z += v[q].z * m[q]; a->w += v[q].w * m[q];
            }
        }
        for (; j < end1; j++) {
            int s0 = g_esrc[j];
            float m0 = g_enorm[j];
            float4 v0 = xr[(size_t)s0 * 32 + lid];
            float4* a = (j < end0) ? &acc0 : &acc1;
            a->x += v0.x * m0; a->y += v0.y * m0; a->z += v0.z * m0; a->w += v0.w * m0;
        }
        uint32_t h0a, l0a, h0b, l0b;
        split2_packed(acc0.x, acc0.y, h0a, l0a);
        split2_packed(acc0.z, acc0.w, h0b, l0b);
        *(uint2*)&sm[SMF_AHI + rl0 * PAD + lid * 4] = make_uint2(h0a, h0b);
        *(uint2*)&sm[SMF_ALO + rl0 * PAD + lid * 4] = make_uint2(l0a, l0b);
        uint32_t h1a, l1a, h1b, l1b;
        split2_packed(acc1.x, acc1.y, h1a, l1a);
        split2_packed(acc1.z, acc1.w, h1b, l1b);
        *(uint2*)&sm[SMF_AHI + (rl0 + 1) * PAD + lid * 4] = make_uint2(h1a, h1b);
        *(uint2*)&sm[SMF_ALO + (rl0 + 1) * PAD + lid * 4] = make_uint2(l1a, l1b);
    }
    __syncthreads();

    // warp grid 4x4
    const int wr = wid >> 2, wc = wid & 3;
    const int g = lid >> 2, tg = lid & 3;
    const int ar0 = wr * 32;

    const int m4 = lid >> 3;
    const int arow = (m4 & 1) * 8 + (lid & 7);
    const int acol = (m4 >> 1) * 8;
    const uint32_t offA0 = (uint32_t)(((ar0 + arow) * PAD + acol) * 2);
    const uint32_t offA1 = (uint32_t)(((ar0 + 16 + arow) * PAD + acol) * 2);
    const int brow = (m4 >> 1) * 8 + (lid & 7);
    const int bcol = (m4 & 1) * 8;

    // ---------- MMA1: warp tile 32x32 at (ar0, nc1) ----------
    {
        const int nc1 = wc * 32;
        uint32_t offB[2];
#pragma unroll
        for (int bi = 0; bi < 2; bi++)
            offB[bi] = (uint32_t)(((nc1 + bi * 16 + brow) * PAD + bcol) * 2);

        float acc[2][4][4];
#pragma unroll
        for (int mi = 0; mi < 2; mi++)
#pragma unroll
            for (int ni = 0; ni < 4; ni++)
#pragma unroll
                for (int j = 0; j < 4; j++) acc[mi][ni][j] = 0.f;

#pragma unroll 1
        for (int pass = 0; pass < 3; pass++) {
            uint32_t abase = sbase + 2 * ((pass == 2) ? SMF_ALO : SMF_AHI);
            uint32_t bbase = sbase + 2 * ((pass == 1) ? SMF_W1L : SMF_W1H);
#pragma unroll 1
            for (int ks = 0; ks < 8; ks++) {
                uint32_t kb = (uint32_t)ks * 32;
                uint32_t a0[4], a1[4];
                ldsm_x4(a0[0], a0[1], a0[2], a0[3], abase + offA0 + kb);
                ldsm_x4(a1[0], a1[1], a1[2], a1[3], abase + offA1 + kb);
#pragma unroll
                for (int bi = 0; bi < 2; bi++) {
                    uint32_t b0, b1, b2, b3;
                    ldsm_x4(b0, b1, b2, b3, bbase + offB[bi] + kb);
                    mma_bf16(acc[0][2 * bi], a0, b0, b1);
                    mma_bf16(acc[0][2 * bi + 1], a0, b2, b3);
                    mma_bf16(acc[1][2 * bi], a1, b0, b1);
                    mma_bf16(acc[1][2 * bi + 1], a1, b2, b3);
                }
            }
        }

        __syncthreads();

        // BN + ReLU + split -> overwrite A planes
#pragma unroll
        for (int mi = 0; mi < 2; mi++)
#pragma unroll
            for (int h = 0; h < 2; h++) {
                int rl = ar0 + mi * 16 + h * 8 + g;
#pragma unroll
                for (int ni = 0; ni < 4; ni++) {
                    int c = nc1 + ni * 8 + tg * 2;
                    float2 sc = *(const float2*)&g_bns[c];
                    float2 tc = *(const float2*)&g_bnt[c];
                    float v0 = fmaxf(acc[mi][ni][h * 2] * sc.x + tc.x, 0.f);
                    float v1 = fmaxf(acc[mi][ni][h * 2 + 1] * sc.y + tc.y, 0.f);
                    uint32_t hi, lo;
                    split2_packed(v0, v1, hi, lo);
                    *(uint32_t*)&sm[SMF_AHI + rl * PAD + c] = hi;
                    *(uint32_t*)&sm[SMF_ALO + rl * PAD + c] = lo;
                }
            }
    }
    __syncthreads();

    // ---------- MMA2: warp tile 32x16 at (ar0, nc2) ----------
    {
        const int nc2 = wc * 16;
        const uint32_t offB0 = (uint32_t)(((nc2 + brow) * PAD + bcol) * 2);

        float acc[2][2][4];
#pragma unroll
        for (int mi = 0; mi < 2; mi++)
#pragma unroll
            for (int ni = 0; ni < 2; ni++)
#pragma unroll
                for (int j = 0; j < 4; j++) acc[mi][ni][j] = 0.f;

#pragma unroll 1
        for (int pass = 0; pass < 3; pass++) {
            uint32_t abase = sbase + 2 * ((pass == 2) ? SMF_ALO : SMF_AHI);
            uint32_t bbase = sbase + 2 * ((pass == 1) ? SMF_W2L : SMF_W2H);
#pragma unroll 1
            for (int ks = 0; ks < 8; ks++) {
                uint32_t kb = (uint32_t)ks * 32;
                uint32_t a0[4], a1[4];
                ldsm_x4(a0[0], a0[1], a0[2], a0[3], abase + offA0 + kb);
                ldsm_x4(a1[0], a1[1], a1[2], a1[3], abase + offA1 + kb);
                uint32_t b0, b1, b2, b3;
                ldsm_x4(b0, b1, b2, b3, bbase + offB0 + kb);
                mma_bf16(acc[0][0], a0, b0, b1);
                mma_bf16(acc[0][1], a0, b2, b3);
                mma_bf16(acc[1][0], a1, b0, b1);
                mma_bf16(acc[1][1], a1, b2, b3);
            }
        }

#pragma unroll
        for (int mi = 0; mi < 2; mi++)
#pragma unroll
            for (int h = 0; h < 2; h++) {
                int r = row0 + ar0 + mi * 16 + g + h * 8;
                if (r < NNODES) {
#pragma unroll
                    for (int ni = 0; ni < 2; ni++) {
                        int c = nc2 + ni * 8 + tg * 2;
                        *(float2*)&g_h2[(size_t)r * 64 + c] =
                            make_float2(acc[mi][ni][h * 2], acc[mi][ni][h * 2 + 1]);
                    }
                }
            }
    }
}

// ---------------- agg2: half-warp per node, unroll-8 ----------------
__global__ void __launch_bounds__(256) agg2_kernel(const float* __restrict__ b2,
                                                   float* __restrict__ out) {
    int t = blockIdx.x * blockDim.x + threadIdx.x;
    int hw = t >> 4;
    int sub = t & 15;
    if (hw >= NNODES) return;
    int beg = g_rowptr[hw], end = g_rowptr[hw + 1];
    float di = g_dinv[hw];
    float d2 = di * di;
    const float4* h2 = (const float4*)g_h2;
    float4 acc = h2[(size_t)hw * 16 + sub];
    acc.x *= d2; acc.y *= d2; acc.z *= d2; acc.w *= d2;
    int j = beg;
    for (; j + 8 <= end; j += 8) {
        int   s[8];
        float m[8];
        float4 v[8];
#pragma unroll
        for (int q = 0; q < 8; q++) { s[q] = g_esrc[j + q]; m[q] = g_enorm[j + q]; }
#pragma unroll
        for (int q = 0; q < 8; q++) v[q] = h2[(size_t)s[q] * 16 + sub];
#pragma unroll
        for (int q = 0; q < 8; q++) {
            acc.x += v[q].x * m[q]; acc.y += v[q].y * m[q];
            acc.z += v[q].z * m[q]; acc.w += v[q].w * m[q];
        }
    }
    for (; j < end; j++) {
        int s0 = g_esrc[j];
        float m0 = g_enorm[j];
        float4 v0 = h2[(size_t)s0 * 16 + sub];
        acc.x += v0.x * m0; acc.y += v0.y * m0; acc.z += v0.z * m0; acc.w += v0.w * m0;
    }
    float4 bv = ((const float4*)b2)[sub];
    ((float4*)out)[(size_t)hw * 16 + sub] =
        make_float4(acc.x + bv.x, acc.y + bv.y, acc.z + bv.z, acc.w + bv.w);
}

// ---------------- launch ----------------
extern "C" void kernel_launch(void* const* d_in, const int* in_sizes, int n_in,
                              void* d_out, int out_size) {
    const float* x     = (const float*)d_in[0];
    const void*  ei    = d_in[1];
    const float* W1    = (const float*)d_in[2];
    const float* b1    = (const float*)d_in[3];
    const float* gamma = (const float*)d_in[4];
    const float* beta  = (const float*)d_in[5];
    const float* rmean = (const float*)d_in[6];
    const float* rvar  = (const float*)d_in[7];
    const float* W2    = (const float*)d_in[8];
    const float* b2    = (const float*)d_in[9];
    float* out = (float*)d_out;

    const int E = in_sizes[1] / 2;

    cudaFuncSetAttribute(fused_kernel, cudaFuncAttributeMaxDynamicSharedMemorySize, SMF_TOTAL);

    int nblk = (NNODES + 255) / 256;  // 391
    detectw_kernel<<<64, 256>>>(ei, W1, W2);
    deg_count_kernel<<<(E + 255) / 256, 256>>>(ei, E);
    dinv_scan1_kernel<<<nblk, 256>>>(b1, gamma, beta, rmean, rvar);
    scan2_kernel<<<1, 512>>>(nblk);
    scan3_kernel<<<nblk, 256>>>(E);
    permute_kernel<<<(E + 255) / 256, 256>>>(ei, E);

    int gblk = (NNODES + 127) / 128;  // 782
    fused_kernel<<<gblk, 512, SMF_TOTAL>>>(x);

    {
        long long th = (long long)NNODES * 16;
        agg2_kernel<<<(int)((th + 255) / 256), 256>>>(b2, out);
    }
}